// round 11
// baseline (speedup 1.0000x reference)
#include <cuda_runtime.h>
#include <cuda_fp16.h>

// Problem sizes
#define Bn   256
#define Tn   512
#define EMBn 64
#define HSn  512
#define VSn  128

// 8 row-groups (32 batch rows) x 16 col-tiles (32 hidden cols) = 128 CTAs
#define GRID   128
#define NGROUP 8
#define GSIZE  16
#define BLOCKT 512
#define WS     808           // W plane row stride in u32 kpairs (800 + pad)
#define HPS    512           // packed-h row stride in u32 (256 kpairs * 2)
#define RS     296           // recurrence reduction stride
#define WS2    264           // FC B plane row stride
#define RS2    672           // FC reduction stride

#define SMEM_U32   (2 * 32 * WS + 5120)
#define SMEM_BYTES (SMEM_U32 * 4)         // 227,328 B

typedef unsigned int u32;

// -------- persistent device state ----------------------------------------
__device__ u32 g_h0p[2][Bn * HPS];                  // ping-pong packed h0
__device__ u32 g_outsp[(size_t)Tn * Bn * HPS];      // packed h1 history
__device__ u32 g_embp[VSn * EMBn];                  // packed embedding
struct PadCnt { unsigned v; unsigned pad[31]; };
__device__ PadCnt g_gcnt[NGROUP];
__device__ volatile unsigned g_gphase[NGROUP * 32];
__device__ unsigned g_allcnt;
__device__ volatile unsigned g_allphase;

__device__ __forceinline__ void group_sync(int g) {
    __threadfence();
    __syncthreads();
    if (threadIdx.x == 0) {
        unsigned ph = g_gphase[g * 32];
        if (atomicAdd(&g_gcnt[g].v, 1u) == GSIZE - 1u) {
            g_gcnt[g].v = 0u;
            __threadfence();
            g_gphase[g * 32] = ph + 1u;
        } else {
            while (g_gphase[g * 32] == ph) { }
        }
    }
    __syncthreads();
}

__device__ __forceinline__ void grid_sync_all() {
    __threadfence();
    __syncthreads();
    if (threadIdx.x == 0) {
        unsigned ph = g_allphase;
        if (atomicAdd(&g_allcnt, 1u) == GRID - 1u) {
            g_allcnt = 0u;
            __threadfence();
            g_allphase = ph + 1u;
        } else {
            while (g_allphase == ph) { }
        }
    }
    __syncthreads();
}

// -------- fp16 split + mma helpers ---------------------------------------
__device__ __forceinline__ void split2(float x, float y, u32& hi, u32& lo) {
    __half hx = __float2half_rn(x), hy = __float2half_rn(y);
    __half lx = __float2half_rn(x - __half2float(hx));
    __half ly = __float2half_rn(y - __half2float(hy));
    __half2 h = __halves2half2(hx, hy), l = __halves2half2(lx, ly);
    hi = *(u32*)&h; lo = *(u32*)&l;
}

__device__ __forceinline__ int permslot(int kp) {
    int p = kp & 7;
    return (kp & ~7) + ((p < 4) ? 2 * p : 2 * p - 7);
}

__device__ __forceinline__ void mma16816(float c[4],
                                         u32 a0, u32 a1, u32 a2, u32 a3,
                                         u32 b0, u32 b1) {
    asm volatile(
        "mma.sync.aligned.m16n8k16.row.col.f32.f16.f16.f32 "
        "{%0,%1,%2,%3}, {%4,%5,%6,%7}, {%8,%9}, {%0,%1,%2,%3};"
        : "+f"(c[0]), "+f"(c[1]), "+f"(c[2]), "+f"(c[3])
        : "r"(a0), "r"(a1), "r"(a2), "r"(a3), "r"(b0), "r"(b1));
}

// One chunk, this warp's k16 block, 2 n-blocks. The 3 split products go to
// 3 INDEPENDENT accumulator sets (a[0]=AhBh, a[1]=AhBl, a[2]=AlBh) so every
// MMA in a chunk is dependency-free; sets are summed once in the epilogue.
__device__ __forceinline__ void chunk_mma3(uint4 u0, uint4 u1,
                                           const u32* __restrict__ Whi,
                                           const u32* __restrict__ Wlo,
                                           int bbase, float a[3][2][4]) {
    #pragma unroll
    for (int jl = 0; jl < 2; ++jl) {
        uint2 Bh = *(const uint2*)(Whi + bbase + jl * (8 * WS));
        uint2 Bl = *(const uint2*)(Wlo + bbase + jl * (8 * WS));
        mma16816(a[0][jl], u0.x, u1.x, u0.z, u1.z, Bh.x, Bh.y);  // Ah*Bh
        mma16816(a[1][jl], u0.x, u1.x, u0.z, u1.z, Bl.x, Bl.y);  // Ah*Bl
        mma16816(a[2][jl], u0.y, u1.y, u0.w, u1.w, Bh.x, Bh.y);  // Al*Bh
    }
}

__device__ __forceinline__ void zero3(float a[3][2][4]) {
    #pragma unroll
    for (int s = 0; s < 3; ++s)
        #pragma unroll
        for (int j = 0; j < 2; ++j)
            #pragma unroll
            for (int r = 0; r < 4; ++r) a[s][j][r] = 0.f;
}

__device__ __forceinline__ void sum3(const float a[3][2][4], float o[2][4]) {
    #pragma unroll
    for (int j = 0; j < 2; ++j)
        #pragma unroll
        for (int r = 0; r < 4; ++r)
            o[j][r] = a[0][j][r] + a[1][j][r] + a[2][j][r];
}

// Reduction + bias + tanh + packed (hi,lo) store. One uint2 / thread.
// NOTE: no trailing sync — caller provides separation before red reuse.
__device__ __forceinline__ void epilogue_one(float acc[2][4], float* red,
                                             int wid, int lane, int rbase,
                                             float ba, float bb,
                                             size_t po, u32* __restrict__ destp) {
    float* st = red + wid * RS + lane * 9;
    st[0] = acc[0][0]; st[1] = acc[0][1]; st[2] = acc[0][2]; st[3] = acc[0][3];
    st[4] = acc[1][0]; st[5] = acc[1][1]; st[6] = acc[1][2]; st[7] = acc[1][3];
    __syncthreads();
    float s0 = 0.f, s1 = 0.f;
    #pragma unroll
    for (int k = 0; k < 4; ++k) {
        const float* q = red + rbase + k * (4 * RS);
        s0 += q[0]; s1 += q[1];
    }
    u32 hi, lo;
    split2(tanhf(s0 + ba), tanhf(s1 + bb), hi, lo);
    *(uint2*)(destp + po) = make_uint2(hi, lo);
}

// Fused phase: L1(t) [h0(t) @ Wih1 + h1(t-1) @ Whh1] and
//              L0(t+1) [emb(t+1) @ Wih0 + h0(t) @ Whh0].
// A-chunk stream: [emb?] + 8 h0 chunks + [8 h1prev chunks?]. h0 loaded once.
template<bool DOL0, bool DOH1P>
__device__ __forceinline__ void phase_mma(
    int xi0, int xi1,
    const u32* __restrict__ h0c0, const u32* __restrict__ h0c1,
    const u32* __restrict__ h1p0, const u32* __restrict__ h1p1,
    const u32* __restrict__ Whi, const u32* __restrict__ Wlo,
    int bcol, int uoff,
    float aL1[3][2][4], float aL0[3][2][4])
{
    constexpr int NCH = (DOL0 ? 9 : 8) + (DOH1P ? 8 : 0);
    auto addr0 = [&](int i) -> const u32* {
        if (DOL0 && i == 0) return g_embp + xi0 * EMBn + uoff;
        int base = DOL0 ? i - 1 : i;
        return (base < 8) ? (h0c0 + base * 64) : (h1p0 + (base - 8) * 64);
    };
    auto addr1 = [&](int i) -> const u32* {
        if (DOL0 && i == 0) return g_embp + xi1 * EMBn + uoff;
        int base = DOL0 ? i - 1 : i;
        return (base < 8) ? (h0c1 + base * 64) : (h1p1 + (base - 8) * 64);
    };
    uint4 cur0 = __ldcg((const uint4*)addr0(0));
    uint4 cur1 = __ldcg((const uint4*)addr1(0));
    uint4 nxt0 = cur0, nxt1 = cur1;
    if (NCH > 1) {
        nxt0 = __ldcg((const uint4*)addr0(1));
        nxt1 = __ldcg((const uint4*)addr1(1));
    }
    #pragma unroll
    for (int i = 0; i < NCH; ++i) {
        uint4 t0 = cur0, t1 = cur1;
        if (i + 2 < NCH) {
            t0 = __ldcg((const uint4*)addr0(i + 2));
            t1 = __ldcg((const uint4*)addr1(i + 2));
        }
        if (DOL0 && i == 0) {
            chunk_mma3(cur0, cur1, Whi, Wlo, bcol, aL0);           // emb @ Wih0
        } else {
            const int base = DOL0 ? i - 1 : i;
            if (base < 8) {
                chunk_mma3(cur0, cur1, Whi, Wlo,
                           bcol + (288 + base * 32), aL1);          // h0 @ Wih1
                if (DOL0)
                    chunk_mma3(cur0, cur1, Whi, Wlo,
                               bcol + (32 + base * 32), aL0);       // h0 @ Whh0
            } else {
                chunk_mma3(cur0, cur1, Whi, Wlo,
                           bcol + (544 + (base - 8) * 32), aL1);    // h1p @ Whh1
            }
        }
        cur0 = nxt0; cur1 = nxt1; nxt0 = t0; nxt1 = t1;
    }
}

extern __shared__ u32 smem_u[];

__global__ void __launch_bounds__(BLOCKT, 1) rnn_persistent_kernel(
    const int*   __restrict__ x,
    const float* __restrict__ emb,
    const float* __restrict__ W_ih0, const float* __restrict__ b_ih0,
    const float* __restrict__ W_hh0, const float* __restrict__ b_hh0,
    const float* __restrict__ W_ih1, const float* __restrict__ b_ih1,
    const float* __restrict__ W_hh1, const float* __restrict__ b_hh1,
    const float* __restrict__ W_fc,  const float* __restrict__ b_fc,
    float* __restrict__ out)
{
    u32*   Whi = smem_u;                       // [32 cols][WS]
    u32*   Wlo = smem_u + 32 * WS;
    float* red = (float*)(smem_u + 64 * WS);   // 5120 floats scratch

    const int tid  = threadIdx.x;
    const int cta  = blockIdx.x;
    const int grp  = cta >> 4;
    const int row0 = grp * 32;
    const int col0 = (cta & 15) * 32;

    // ---- weight slice -> SMEM as fp16 hi/lo, fragment-permuted ----------
    {
        const int c  = tid & 31;
        const int pp = tid >> 5;
        for (int pb = 0; pb < 800; pb += 16) {
            int kp = pb + pp;
            int k  = kp * 2;
            const float* src; int kr;
            if      (k < 64)   { src = W_ih0; kr = k; }
            else if (k < 576)  { src = W_hh0; kr = k - 64; }
            else if (k < 1088) { src = W_ih1; kr = k - 576; }
            else               { src = W_hh1; kr = k - 1088; }
            float w0 = src[(size_t)kr * HSn + col0 + c];
            float w1 = src[(size_t)(kr + 1) * HSn + col0 + c];
            u32 hi, lo;
            split2(w0, w1, hi, lo);
            int pos = permslot(kp);
            Whi[c * WS + pos] = hi;
            Wlo[c * WS + pos] = lo;
        }
    }

    // ---- packed embedding precompute: CTA i owns vocab row i -------------
    if (tid < 32) {
        float w0 = emb[cta * EMBn + 2 * tid];
        float w1 = emb[cta * EMBn + 2 * tid + 1];
        u32 hi, lo;
        split2(w0, w1, hi, lo);
        int slot = permslot(tid);
        g_embp[cta * EMBn + slot * 2]     = hi;
        g_embp[cta * EMBn + slot * 2 + 1] = lo;
    }
    grid_sync_all();

    // ---- warp decomposition: wid = mh + 2*nh + 4*ks ----------------------
    const int wid  = tid >> 5;
    const int lane = tid & 31;
    const int mh   = wid & 1;
    const int nh   = (wid >> 1) & 1;
    const int ks   = wid >> 2;
    const int g    = lane >> 2;
    const int kt   = lane & 3;

    const int fr0  = row0 + mh * 16 + g;
    const int fr1  = fr0 + 8;
    const int uoff = (ks * 8 + 2 * kt) * 2;
    const int bcol = (nh * 16 + g) * WS + 2 * kt + ks * 8;

    // epilogue mapping (validated R8-R10 layout)
    const int mh_r = wid & 1;
    const int jg   = (wid >> 1) & 3;
    const int rh   = wid >> 3;
    const int gr   = lane >> 2, ktr = lane & 3;
    const int er   = row0 + mh_r * 16 + rh * 8 + gr;
    const int ec0  = col0 + jg * 8 + 2 * ktr;
    const size_t po = (size_t)er * HPS + permslot(ec0 >> 1) * 2;
    const int rbase = (mh_r + 2 * (jg >> 1)) * RS + (gr * 4 + ktr) * 9
                    + (jg & 1) * 4 + rh * 2;
    const float l0ba = b_ih0[ec0] + b_hh0[ec0];
    const float l0bb = b_ih0[ec0 + 1] + b_hh0[ec0 + 1];
    const float l1ba = b_ih1[ec0] + b_hh1[ec0];
    const float l1bb = b_ih1[ec0 + 1] + b_hh1[ec0 + 1];

    // ===== pre-loop phase: L0(0) = tanh(emb(0) @ Wih0 + b) ===============
    {
        int xi0 = x[fr0 * Tn + 0];
        int xi1 = x[fr1 * Tn + 0];
        uint4 e0 = __ldcg((const uint4*)(g_embp + xi0 * EMBn + uoff));
        uint4 e1 = __ldcg((const uint4*)(g_embp + xi1 * EMBn + uoff));
        float aL0[3][2][4];
        zero3(aL0);
        chunk_mma3(e0, e1, Whi, Wlo, bcol, aL0);
        float s0v[2][4];
        sum3(aL0, s0v);
        epilogue_one(s0v, red, wid, lane, rbase, l0ba, l0bb, po, g_h0p[0]);
    }
    group_sync(grp);

    // ===== main loop: one fused phase per step ===========================
    for (int t = 0; t < Tn; ++t) {
        const u32* h0cur = g_h0p[t & 1];
        u32*       h0nxt = g_h0p[(t & 1) ^ 1];
        const u32* h1prv = g_outsp + ((long)t - 1) * (long)(Bn * HPS);
        u32*       h1cur = g_outsp + (size_t)t * (Bn * HPS);

        const u32* h0c0 = h0cur + (size_t)fr0 * HPS + uoff;
        const u32* h0c1 = h0cur + (size_t)fr1 * HPS + uoff;
        const u32* h1p0 = h1prv + (size_t)fr0 * HPS + uoff;
        const u32* h1p1 = h1prv + (size_t)fr1 * HPS + uoff;

        int xi0 = 0, xi1 = 0;
        if (t + 1 < Tn) {
            xi0 = x[fr0 * Tn + t + 1];
            xi1 = x[fr1 * Tn + t + 1];
        }

        float aL1[3][2][4], aL0[3][2][4];
        zero3(aL1);
        zero3(aL0);

        if (t == 0)
            phase_mma<true, false>(xi0, xi1, h0c0, h0c1, h1p0, h1p1,
                                   Whi, Wlo, bcol, uoff, aL1, aL0);
        else if (t + 1 < Tn)
            phase_mma<true, true>(xi0, xi1, h0c0, h0c1, h1p0, h1p1,
                                  Whi, Wlo, bcol, uoff, aL1, aL0);
        else
            phase_mma<false, true>(xi0, xi1, h0c0, h0c1, h1p0, h1p1,
                                   Whi, Wlo, bcol, uoff, aL1, aL0);

        float s1v[2][4];
        sum3(aL1, s1v);
        epilogue_one(s1v, red, wid, lane, rbase, l1ba, l1bb, po, h1cur);
        if (t + 1 < Tn) {
            float s0v[2][4];
            sum3(aL0, s0v);
            __syncthreads();   // red reuse
            epilogue_one(s0v, red, wid, lane, rbase, l0ba, l0bb, po, h0nxt);
        }
        group_sync(grp);       // h1(t), h0(t+1) visible group-wide
    }

    grid_sync_all();

    // ===== final FC via tensor cores: logits = h1 @ W_fc + b_fc ==========
    u32*   Fhi  = smem_u;                      // [64 cols][WS2]
    u32*   Flo  = smem_u + 64 * WS2;
    float* red2 = (float*)(smem_u + 2 * 64 * WS2);

    const int mh_r2 = wid & 1;
    const int jg2   = (wid >> 1) & 7;
    const int base2 = (mh_r2 + 2 * (jg2 >> 2)) * RS2 + (gr * 4 + ktr) * 21
                    + (jg2 & 3) * 4;

    for (int pass = 0; pass < 2; ++pass) {
        __syncthreads();
        for (int i = tid; i < 64 * 256; i += BLOCKT) {
            int cc = i & 63;
            int kp = i >> 6;
            float w0 = W_fc[(size_t)(2 * kp) * VSn + pass * 64 + cc];
            float w1 = W_fc[(size_t)(2 * kp + 1) * VSn + pass * 64 + cc];
            u32 hi, lo;
            split2(w0, w1, hi, lo);
            int slot = permslot(kp);
            Fhi[cc * WS2 + slot] = hi;
            Flo[cc * WS2 + slot] = lo;
        }
        __syncthreads();

        const int cfc = pass * 64 + jg2 * 8 + 2 * ktr;
        const float bfa = b_fc[cfc], bfb = b_fc[cfc + 1];

        for (int ti = 0; ti < 32; ++ti) {
            const int m0 = (cta * 32 + ti) * 32;
            const u32* a0p = g_outsp + (size_t)(m0 + mh * 16 + g) * HPS + uoff;
            const u32* a1p = a0p + 8 * HPS;

            float acc[3][4][4];
            #pragma unroll
            for (int s = 0; s < 3; ++s)
                #pragma unroll
                for (int j = 0; j < 4; ++j)
                    #pragma unroll
                    for (int r = 0; r < 4; ++r) acc[s][j][r] = 0.f;

            uint4 c0 = *(const uint4*)a0p;
            uint4 c1 = *(const uint4*)a1p;
            #pragma unroll 1
            for (int c = 0; c < 8; ++c) {
                uint4 t0 = c0, t1 = c1;
                if (c + 1 < 8) {
                    t0 = *(const uint4*)(a0p + (c + 1) * 64);
                    t1 = *(const uint4*)(a1p + (c + 1) * 64);
                }
                #pragma unroll
                for (int jl = 0; jl < 4; ++jl) {
                    int bb_ = ((nh * 4 + jl) * 8 + g) * WS2 + c * 32
                            + ks * 8 + 2 * kt;
                    uint2 Bh = *(const uint2*)(Fhi + bb_);
                    uint2 Bl = *(const uint2*)(Flo + bb_);
                    mma16816(acc[0][jl], c0.x, c1.x, c0.z, c1.z, Bh.x, Bh.y);
                    mma16816(acc[1][jl], c0.x, c1.x, c0.z, c1.z, Bl.x, Bl.y);
                    mma16816(acc[2][jl], c0.y, c1.y, c0.w, c1.w, Bh.x, Bh.y);
                }
                c0 = t0; c1 = t1;
            }

            {
                float* st = red2 + wid * RS2 + lane * 21;
                #pragma unroll
                for (int jl = 0; jl < 4; ++jl) {
                    st[jl * 4 + 0] = acc[0][jl][0] + acc[1][jl][0] + acc[2][jl][0];
                    st[jl * 4 + 1] = acc[0][jl][1] + acc[1][jl][1] + acc[2][jl][1];
                    st[jl * 4 + 2] = acc[0][jl][2] + acc[1][jl][2] + acc[2][jl][2];
                    st[jl * 4 + 3] = acc[0][jl][3] + acc[1][jl][3] + acc[2][jl][3];
                }
                __syncthreads();
                float r0 = 0.f, r1 = 0.f, r2 = 0.f, r3 = 0.f;
                #pragma unroll
                for (int k = 0; k < 4; ++k) {
                    const float* q = red2 + base2 + k * (4 * RS2);
                    r0 += q[0]; r1 += q[1]; r2 += q[2]; r3 += q[3];
                }
                #pragma unroll
                for (int rh2 = 0; rh2 < 2; ++rh2) {
                    const int m  = m0 + mh_r2 * 16 + rh2 * 8 + gr;
                    const int tt = m >> 8;
                    const int bb = m & 255;
                    float2 v = rh2 ? make_float2(r2 + bfa, r3 + bfb)
                                   : make_float2(r0 + bfa, r1 + bfb);
                    *(float2*)(out + ((size_t)bb * Tn + tt) * VSn + cfc) = v;
                }
                __syncthreads();
            }
        }
    }
}

extern "C" void kernel_launch(void* const* d_in, const int* in_sizes, int n_in,
                              void* d_out, int out_size) {
    const int*   x      = (const int*)  d_in[0];
    const float* emb    = (const float*)d_in[1];
    const float* W_ih0  = (const float*)d_in[2];
    const float* b_ih0  = (const float*)d_in[3];
    const float* W_hh0  = (const float*)d_in[4];
    const float* b_hh0  = (const float*)d_in[5];
    const float* W_ih1  = (const float*)d_in[6];
    const float* b_ih1  = (const float*)d_in[7];
    const float* W_hh1  = (const float*)d_in[8];
    const float* b_hh1  = (const float*)d_in[9];
    const float* W_fc   = (const float*)d_in[10];
    const float* b_fc   = (const float*)d_in[11];
    float* out = (float*)d_out;

    cudaFuncSetAttribute(rnn_persistent_kernel,
                         cudaFuncAttributeMaxDynamicSharedMemorySize, SMEM_BYTES);

    rnn_persistent_kernel<<<GRID, BLOCKT, SMEM_BYTES>>>(
        x, emb, W_ih0, b_ih0, W_hh0, b_hh0,
        W_ih1, b_ih1, W_hh1, b_hh1, W_fc, b_fc, out);
}

// round 12
// speedup vs baseline: 1.1573x; 1.1573x over previous
#include <cuda_runtime.h>
#include <cuda_fp16.h>

// Problem sizes
#define Bn   256
#define Tn   512
#define EMBn 64
#define HSn  512
#define VSn  128

// 8 row-groups (32 batch rows) x 16 col-tiles (32 hidden cols) = 128 CTAs
#define GRID   128
#define NGROUP 8
#define GSIZE  16
#define BLOCKT 256           // 8 warps -> 255-reg budget for deep A prefetch
#define WS     808           // W plane row stride in u32 kpairs (800 + pad)
#define HPS    512           // packed-h row stride in u32 (256 kpairs * 2)
#define RS     544           // recurrence reduction stride (32*17, conflict-free)
#define WS2    264           // FC B plane row stride
#define RS2    1056          // FC reduction stride (32*33)

#define SMEM_U32   (2 * 32 * WS + 5120)
#define SMEM_BYTES (SMEM_U32 * 4)         // 227,328 B

typedef unsigned int u32;

// -------- persistent device state ----------------------------------------
__device__ u32 g_h0p[2][Bn * HPS];                  // ping-pong packed h0
__device__ u32 g_outsp[(size_t)Tn * Bn * HPS];      // packed h1 history
__device__ u32 g_embp[VSn * EMBn];                  // packed embedding
struct PadCnt { unsigned v; unsigned pad[31]; };
__device__ PadCnt g_gcnt[NGROUP];
__device__ volatile unsigned g_gphase[NGROUP * 32];
__device__ unsigned g_allcnt;
__device__ volatile unsigned g_allphase;

__device__ __forceinline__ void group_sync(int g) {
    __threadfence();
    __syncthreads();
    if (threadIdx.x == 0) {
        unsigned ph = g_gphase[g * 32];
        if (atomicAdd(&g_gcnt[g].v, 1u) == GSIZE - 1u) {
            g_gcnt[g].v = 0u;
            __threadfence();
            g_gphase[g * 32] = ph + 1u;
        } else {
            while (g_gphase[g * 32] == ph) { }
        }
    }
    __syncthreads();
}

__device__ __forceinline__ void grid_sync_all() {
    __threadfence();
    __syncthreads();
    if (threadIdx.x == 0) {
        unsigned ph = g_allphase;
        if (atomicAdd(&g_allcnt, 1u) == GRID - 1u) {
            g_allcnt = 0u;
            __threadfence();
            g_allphase = ph + 1u;
        } else {
            while (g_allphase == ph) { }
        }
    }
    __syncthreads();
}

// -------- fp16 split + mma helpers ---------------------------------------
__device__ __forceinline__ void split2(float x, float y, u32& hi, u32& lo) {
    __half hx = __float2half_rn(x), hy = __float2half_rn(y);
    __half lx = __float2half_rn(x - __half2float(hx));
    __half ly = __float2half_rn(y - __half2float(hy));
    __half2 h = __halves2half2(hx, hy), l = __halves2half2(lx, ly);
    hi = *(u32*)&h; lo = *(u32*)&l;
}

__device__ __forceinline__ int permslot(int kp) {
    int p = kp & 7;
    return (kp & ~7) + ((p < 4) ? 2 * p : 2 * p - 7);
}

__device__ __forceinline__ void mma16816(float c[4],
                                         u32 a0, u32 a1, u32 a2, u32 a3,
                                         u32 b0, u32 b1) {
    asm volatile(
        "mma.sync.aligned.m16n8k16.row.col.f32.f16.f16.f32 "
        "{%0,%1,%2,%3}, {%4,%5,%6,%7}, {%8,%9}, {%0,%1,%2,%3};"
        : "+f"(c[0]), "+f"(c[1]), "+f"(c[2]), "+f"(c[3])
        : "r"(a0), "r"(a1), "r"(a2), "r"(a3), "r"(b0), "r"(b1));
}

// One chunk, this warp's k16 block, ALL 4 n-blocks (3 split products each).
__device__ __forceinline__ void chunk_mma4(uint4 u0, uint4 u1,
                                           const u32* __restrict__ Whi,
                                           const u32* __restrict__ Wlo,
                                           int bbase, float acc[4][4]) {
    #pragma unroll
    for (int jl = 0; jl < 4; ++jl) {
        uint2 Bh = *(const uint2*)(Whi + bbase + jl * (8 * WS));
        uint2 Bl = *(const uint2*)(Wlo + bbase + jl * (8 * WS));
        mma16816(acc[jl], u0.x, u1.x, u0.z, u1.z, Bh.x, Bh.y);  // Ah*Bh
        mma16816(acc[jl], u0.x, u1.x, u0.z, u1.z, Bl.x, Bl.y);  // Ah*Bl
        mma16816(acc[jl], u0.y, u1.y, u0.w, u1.w, Bh.x, Bh.y);  // Al*Bh
    }
}

__device__ __forceinline__ void zero4(float a[4][4]) {
    #pragma unroll
    for (int j = 0; j < 4; ++j)
        #pragma unroll
        for (int r = 0; r < 4; ++r) a[j][r] = 0.f;
}

// K-split reduction + bias + tanh + 2 packed (hi,lo) stores per thread.
// NOTE: no trailing sync — caller provides separation before red reuse.
__device__ __forceinline__ void epilogue_one(const float acc[4][4], float* red,
                                             int wid, int lane, int rbase,
                                             float ba, float bb,
                                             size_t po0, size_t po1,
                                             u32* __restrict__ destp) {
    float* st = red + wid * RS + lane * 17;
    #pragma unroll
    for (int jl = 0; jl < 4; ++jl) {
        st[jl * 4 + 0] = acc[jl][0]; st[jl * 4 + 1] = acc[jl][1];
        st[jl * 4 + 2] = acc[jl][2]; st[jl * 4 + 3] = acc[jl][3];
    }
    __syncthreads();
    float s00 = 0.f, s01 = 0.f, s10 = 0.f, s11 = 0.f;
    #pragma unroll
    for (int k = 0; k < 4; ++k) {
        const float* q = red + rbase + k * (2 * RS);
        s00 += q[0]; s01 += q[1]; s10 += q[2]; s11 += q[3];
    }
    u32 hi, lo;
    split2(tanhf(s00 + ba), tanhf(s01 + bb), hi, lo);
    *(uint2*)(destp + po0) = make_uint2(hi, lo);
    split2(tanhf(s10 + ba), tanhf(s11 + bb), hi, lo);
    *(uint2*)(destp + po1) = make_uint2(hi, lo);
}

// Fused phase: L1(t) [h0(t)@Wih1 + h1(t-1)@Whh1] and L0(t+1) [emb@Wih0 + h0(t)@Whh0].
// ALL A-operand LDGs issued up front (MLP ~= 2*NCH) — one latency round trip.
template<bool DOL0, bool DOH1P>
__device__ __forceinline__ void phase_mma(
    int xi0, int xi1,
    const u32* __restrict__ h0c0, const u32* __restrict__ h0c1,
    const u32* __restrict__ h1p0, const u32* __restrict__ h1p1,
    const u32* __restrict__ Whi, const u32* __restrict__ Wlo,
    int bcol, int uoff,
    float aL1[4][4], float aL0[4][4])
{
    constexpr int NCH = (DOL0 ? 9 : 8) + (DOH1P ? 8 : 0);
    uint4 A0[NCH], A1[NCH];
    #pragma unroll
    for (int i = 0; i < NCH; ++i) {
        const u32 *p0, *p1;
        if (DOL0 && i == 0) {
            p0 = g_embp + xi0 * EMBn + uoff;
            p1 = g_embp + xi1 * EMBn + uoff;
        } else {
            int base = DOL0 ? i - 1 : i;
            if (base < 8) { p0 = h0c0 + base * 64; p1 = h0c1 + base * 64; }
            else { p0 = h1p0 + (base - 8) * 64; p1 = h1p1 + (base - 8) * 64; }
        }
        A0[i] = __ldcg((const uint4*)p0);
        A1[i] = __ldcg((const uint4*)p1);
    }
    #pragma unroll
    for (int i = 0; i < NCH; ++i) {
        if (DOL0 && i == 0) {
            chunk_mma4(A0[i], A1[i], Whi, Wlo, bcol, aL0);          // emb @ Wih0
        } else {
            const int base = DOL0 ? i - 1 : i;
            if (base < 8) {
                chunk_mma4(A0[i], A1[i], Whi, Wlo,
                           bcol + (288 + base * 32), aL1);           // h0 @ Wih1
                if (DOL0)
                    chunk_mma4(A0[i], A1[i], Whi, Wlo,
                               bcol + (32 + base * 32), aL0);        // h0 @ Whh0
            } else {
                chunk_mma4(A0[i], A1[i], Whi, Wlo,
                           bcol + (544 + (base - 8) * 32), aL1);     // h1p @ Whh1
            }
        }
    }
}

extern __shared__ u32 smem_u[];

__global__ void __launch_bounds__(BLOCKT, 1) rnn_persistent_kernel(
    const int*   __restrict__ x,
    const float* __restrict__ emb,
    const float* __restrict__ W_ih0, const float* __restrict__ b_ih0,
    const float* __restrict__ W_hh0, const float* __restrict__ b_hh0,
    const float* __restrict__ W_ih1, const float* __restrict__ b_ih1,
    const float* __restrict__ W_hh1, const float* __restrict__ b_hh1,
    const float* __restrict__ W_fc,  const float* __restrict__ b_fc,
    float* __restrict__ out)
{
    u32*   Whi = smem_u;                       // [32 cols][WS]
    u32*   Wlo = smem_u + 32 * WS;
    float* red = (float*)(smem_u + 64 * WS);   // 5120 floats scratch

    const int tid  = threadIdx.x;
    const int cta  = blockIdx.x;
    const int grp  = cta >> 4;
    const int row0 = grp * 32;
    const int col0 = (cta & 15) * 32;

    // ---- weight slice -> SMEM as fp16 hi/lo, fragment-permuted ----------
    {
        const int c  = tid & 31;
        const int pp = tid >> 5;               // 0..7
        for (int pb = 0; pb < 800; pb += 8) {
            int kp = pb + pp;
            int k  = kp * 2;
            const float* src; int kr;
            if      (k < 64)   { src = W_ih0; kr = k; }
            else if (k < 576)  { src = W_hh0; kr = k - 64; }
            else if (k < 1088) { src = W_ih1; kr = k - 576; }
            else               { src = W_hh1; kr = k - 1088; }
            float w0 = src[(size_t)kr * HSn + col0 + c];
            float w1 = src[(size_t)(kr + 1) * HSn + col0 + c];
            u32 hi, lo;
            split2(w0, w1, hi, lo);
            int pos = permslot(kp);
            Whi[c * WS + pos] = hi;
            Wlo[c * WS + pos] = lo;
        }
    }

    // ---- packed embedding precompute: CTA i owns vocab row i -------------
    if (tid < 32) {
        float w0 = emb[cta * EMBn + 2 * tid];
        float w1 = emb[cta * EMBn + 2 * tid + 1];
        u32 hi, lo;
        split2(w0, w1, hi, lo);
        int slot = permslot(tid);
        g_embp[cta * EMBn + slot * 2]     = hi;
        g_embp[cta * EMBn + slot * 2 + 1] = lo;
    }
    grid_sync_all();

    // ---- warp decomposition: wid = mh + 2*ks (8 warps, 4 n-blocks each) --
    const int wid  = tid >> 5;
    const int lane = tid & 31;
    const int mh   = wid & 1;
    const int ks   = wid >> 1;            // 0..3 K-split
    const int g    = lane >> 2;
    const int kt   = lane & 3;

    const int fr0  = row0 + mh * 16 + g;
    const int fr1  = fr0 + 8;
    const int uoff = (ks * 8 + 2 * kt) * 2;
    const int bcol = g * WS + 2 * kt + ks * 8;

    // epilogue mapping: read warp -> (mh_r, jg); lane -> (gr, ktr)
    const int mh_r = wid & 1;
    const int jg   = wid >> 1;            // 0..3 col block
    const int gr   = lane >> 2, ktr = lane & 3;
    const int er0  = row0 + mh_r * 16 + gr;
    const int ec0  = col0 + jg * 8 + 2 * ktr;
    const size_t po0 = (size_t)er0 * HPS + permslot(ec0 >> 1) * 2;
    const size_t po1 = (size_t)(er0 + 8) * HPS + permslot(ec0 >> 1) * 2;
    const int rbase = mh_r * RS + (gr * 4 + ktr) * 17 + jg * 4;
    const float l0ba = b_ih0[ec0] + b_hh0[ec0];
    const float l0bb = b_ih0[ec0 + 1] + b_hh0[ec0 + 1];
    const float l1ba = b_ih1[ec0] + b_hh1[ec0];
    const float l1bb = b_ih1[ec0 + 1] + b_hh1[ec0 + 1];

    // ===== pre-loop phase: L0(0) = tanh(emb(0) @ Wih0 + b) ===============
    {
        int xi0 = x[fr0 * Tn + 0];
        int xi1 = x[fr1 * Tn + 0];
        uint4 e0 = __ldcg((const uint4*)(g_embp + xi0 * EMBn + uoff));
        uint4 e1 = __ldcg((const uint4*)(g_embp + xi1 * EMBn + uoff));
        float aL0[4][4];
        zero4(aL0);
        chunk_mma4(e0, e1, Whi, Wlo, bcol, aL0);
        epilogue_one(aL0, red, wid, lane, rbase, l0ba, l0bb, po0, po1,
                     g_h0p[0]);
    }
    group_sync(grp);

    // ===== main loop: one fused phase per step ===========================
    for (int t = 0; t < Tn; ++t) {
        const u32* h0cur = g_h0p[t & 1];
        u32*       h0nxt = g_h0p[(t & 1) ^ 1];
        const u32* h1prv = g_outsp + ((long)t - 1) * (long)(Bn * HPS);
        u32*       h1cur = g_outsp + (size_t)t * (Bn * HPS);

        const u32* h0c0 = h0cur + (size_t)fr0 * HPS + uoff;
        const u32* h0c1 = h0cur + (size_t)fr1 * HPS + uoff;
        const u32* h1p0 = h1prv + (size_t)fr0 * HPS + uoff;
        const u32* h1p1 = h1prv + (size_t)fr1 * HPS + uoff;

        int xi0 = 0, xi1 = 0;
        if (t + 1 < Tn) {
            xi0 = x[fr0 * Tn + t + 1];
            xi1 = x[fr1 * Tn + t + 1];
        }

        float aL1[4][4], aL0[4][4];
        zero4(aL1);
        zero4(aL0);

        if (t == 0)
            phase_mma<true, false>(xi0, xi1, h0c0, h0c1, h1p0, h1p1,
                                   Whi, Wlo, bcol, uoff, aL1, aL0);
        else if (t + 1 < Tn)
            phase_mma<true, true>(xi0, xi1, h0c0, h0c1, h1p0, h1p1,
                                  Whi, Wlo, bcol, uoff, aL1, aL0);
        else
            phase_mma<false, true>(xi0, xi1, h0c0, h0c1, h1p0, h1p1,
                                   Whi, Wlo, bcol, uoff, aL1, aL0);

        epilogue_one(aL1, red, wid, lane, rbase, l1ba, l1bb, po0, po1, h1cur);
        if (t + 1 < Tn) {
            __syncthreads();   // red reuse
            epilogue_one(aL0, red, wid, lane, rbase, l0ba, l0bb, po0, po1,
                         h0nxt);
        }
        group_sync(grp);       // h1(t), h0(t+1) visible group-wide
    }

    grid_sync_all();

    // ===== final FC via tensor cores: logits = h1 @ W_fc + b_fc ==========
    u32*   Fhi  = smem_u;                      // [64 cols][WS2]
    u32*   Flo  = smem_u + 64 * WS2;
    float* red2 = (float*)(smem_u + 2 * 64 * WS2);   // 8*RS2 floats

    const int jg2   = wid;                     // 0..7 col block of the pass
    const int base2 = (gr * 4 + ktr) * 33 + jg2 * 4;

    for (int pass = 0; pass < 2; ++pass) {
        __syncthreads();
        for (int i = tid; i < 64 * 256; i += BLOCKT) {
            int cc = i & 63;
            int kp = i >> 6;
            float w0 = W_fc[(size_t)(2 * kp) * VSn + pass * 64 + cc];
            float w1 = W_fc[(size_t)(2 * kp + 1) * VSn + pass * 64 + cc];
            u32 hi, lo;
            split2(w0, w1, hi, lo);
            int slot = permslot(kp);
            Fhi[cc * WS2 + slot] = hi;
            Flo[cc * WS2 + slot] = lo;
        }
        __syncthreads();

        const int cfc = pass * 64 + jg2 * 8 + 2 * ktr;
        const float bfa = b_fc[cfc], bfb = b_fc[cfc + 1];

        for (int ti = 0; ti < 32; ++ti) {
            const int m0 = (cta * 32 + ti) * 32;
            const u32* a0p = g_outsp + (size_t)(m0 + mh * 16 + g) * HPS + uoff;
            const u32* a1p = a0p + 8 * HPS;

            // burst-load all 8 K-chunks of A
            uint4 C0[8], C1[8];
            #pragma unroll
            for (int c = 0; c < 8; ++c) {
                C0[c] = __ldcg((const uint4*)(a0p + c * 64));
                C1[c] = __ldcg((const uint4*)(a1p + c * 64));
            }

            float acc[8][4];
            #pragma unroll
            for (int j = 0; j < 8; ++j)
                #pragma unroll
                for (int r = 0; r < 4; ++r) acc[j][r] = 0.f;

            #pragma unroll
            for (int c = 0; c < 8; ++c) {
                #pragma unroll
                for (int jl = 0; jl < 8; ++jl) {
                    int bb_ = (jl * 8 + g) * WS2 + c * 32 + ks * 8 + 2 * kt;
                    uint2 Bh = *(const uint2*)(Fhi + bb_);
                    uint2 Bl = *(const uint2*)(Flo + bb_);
                    mma16816(acc[jl], C0[c].x, C1[c].x, C0[c].z, C1[c].z,
                             Bh.x, Bh.y);
                    mma16816(acc[jl], C0[c].x, C1[c].x, C0[c].z, C1[c].z,
                             Bl.x, Bl.y);
                    mma16816(acc[jl], C0[c].y, C1[c].y, C0[c].w, C1[c].w,
                             Bh.x, Bh.y);
                }
            }

            {
                float* st = red2 + wid * RS2 + lane * 33;
                #pragma unroll
                for (int jl = 0; jl < 8; ++jl) {
                    st[jl * 4 + 0] = acc[jl][0]; st[jl * 4 + 1] = acc[jl][1];
                    st[jl * 4 + 2] = acc[jl][2]; st[jl * 4 + 3] = acc[jl][3];
                }
                __syncthreads();
                #pragma unroll
                for (int mloc = 0; mloc < 2; ++mloc) {
                    float r0 = 0.f, r1 = 0.f, r2 = 0.f, r3 = 0.f;
                    #pragma unroll
                    for (int k = 0; k < 4; ++k) {
                        const float* q = red2 + (mloc + 2 * k) * RS2 + base2;
                        r0 += q[0]; r1 += q[1]; r2 += q[2]; r3 += q[3];
                    }
                    #pragma unroll
                    for (int rh2 = 0; rh2 < 2; ++rh2) {
                        const int m  = m0 + mloc * 16 + rh2 * 8 + gr;
                        const int tt = m >> 8;
                        const int bb = m & 255;
                        float2 v = rh2 ? make_float2(r2 + bfa, r3 + bfb)
                                       : make_float2(r0 + bfa, r1 + bfb);
                        *(float2*)(out + ((size_t)bb * Tn + tt) * VSn + cfc) = v;
                    }
                }
                __syncthreads();
            }
        }
    }
}

extern "C" void kernel_launch(void* const* d_in, const int* in_sizes, int n_in,
                              void* d_out, int out_size) {
    const int*   x      = (const int*)  d_in[0];
    const float* emb    = (const float*)d_in[1];
    const float* W_ih0  = (const float*)d_in[2];
    const float* b_ih0  = (const float*)d_in[3];
    const float* W_hh0  = (const float*)d_in[4];
    const float* b_hh0  = (const float*)d_in[5];
    const float* W_ih1  = (const float*)d_in[6];
    const float* b_ih1  = (const float*)d_in[7];
    const float* W_hh1  = (const float*)d_in[8];
    const float* b_hh1  = (const float*)d_in[9];
    const float* W_fc   = (const float*)d_in[10];
    const float* b_fc   = (const float*)d_in[11];
    float* out = (float*)d_out;

    cudaFuncSetAttribute(rnn_persistent_kernel,
                         cudaFuncAttributeMaxDynamicSharedMemorySize, SMEM_BYTES);

    rnn_persistent_kernel<<<GRID, BLOCKT, SMEM_BYTES>>>(
        x, emb, W_ih0, b_ih0, W_hh0, b_hh0,
        W_ih1, b_ih1, W_hh1, b_hh1, W_fc, b_fc, out);
}